// round 15
// baseline (speedup 1.0000x reference)
#include <cuda_runtime.h>
#include <cuda_fp16.h>
#include <cstdint>

#define DD    128
#define NNB   32
#define WSTR  132              // w_h stride (u32); fragment-major, re-paired k rows
#define SH    72               // nbH row stride (u32); conflict-free LDS.64/STS.64
#define NGRP  4
#define LRELU_ALPHA 0.2f

// w_h : "k-pair row" R = 8c + r (chunk c of 16 k's, r = 0..7):
//   r < 4 : half2 pair of physical k-rows (16c+4r, 16c+4r+1)
//   r >= 4: pair (16c+4(r-4)+2, +3)
//   within row: pos(e) = (e&7)*16 + (e>>3) (u32), conflict-free LDS.128.
// nbH : row n, entry j = half2(nb[n][2j], nb[n][2j+1]); 4 slots per group.
// Dual-batch iteration: one B-fragment load feeds MMAs of BOTH tiles.

__device__ __forceinline__ uint32_t pk_h2(float lo, float hi) {
    __half2 h = __floats2half2_rn(lo, hi);
    return *reinterpret_cast<uint32_t*>(&h);
}

__device__ __forceinline__ void mma_f16(float& c0, float& c1, float& c2, float& c3,
                                        uint32_t a0, uint32_t a1, uint32_t a2, uint32_t a3,
                                        uint32_t b0, uint32_t b1) {
    asm volatile(
        "mma.sync.aligned.m16n8k16.row.col.f32.f16.f16.f32 "
        "{%0,%1,%2,%3}, {%4,%5,%6,%7}, {%8,%9}, {%0,%1,%2,%3};"
        : "+f"(c0), "+f"(c1), "+f"(c2), "+f"(c3)
        : "r"(a0), "r"(a1), "r"(a2), "r"(a3), "r"(b0), "r"(b1));
}

__device__ __forceinline__ void barg(int id) {
    asm volatile("bar.sync %0, 128;" :: "r"(id) : "memory");
}

extern "C" __global__ void __launch_bounds__(512, 1)
gat_h16f(const float* __restrict__ self_v,
         const float* __restrict__ nbv,
         const float* __restrict__ w,
         const float* __restrict__ q,
         float* __restrict__ out,
         int B)
{
    extern __shared__ float sm[];
    uint32_t* w_h  = reinterpret_cast<uint32_t*>(sm);    // 8448 u32
    uint32_t* nbH  = w_h + 64 * WSTR;                    // 4 grp * 4 slot * 32*72 = 36864 u32
    float* scoreP  = sm + 8448 + 36864;                  // 4 grp * 2 b * 128 = 1024 f
    float* alphaP  = scoreP + NGRP * 2 * 128;            // 4 grp * 2 b * 32 = 256 f
    float* hl_s    = alphaP + NGRP * 2 * NNB;            // 4*4 warps * 2 b * 32 f2 = 2048 f

    const int t    = threadIdx.x;
    const int lane = t & 31;
    const int ww   = t >> 5;
    const int g    = ww >> 2;
    const int eb   = ww & 3;
    const int gt   = t & 127;
    const int wrow = gt >> 5;
    const int qr   = lane >> 2;
    const int qc   = lane & 3;
    const int bid  = g + 1;
    const int e_lane = 32 * eb + lane;

    uint32_t* nbH_g = nbH + g * 4 * 32 * SH;
    float*    scoreG = scoreP + g * 2 * 128;
    float*    alphaG = alphaP + g * 2 * NNB;
    float2*   hl_w   = reinterpret_cast<float2*>(hl_s) + (g * 4 + eb) * 2 * NNB;

    // ---- one-time: w -> fp16 re-paired k rows, fragment-major (RN) ----
    {
        #pragma unroll
        for (int i = 0; i < 16; ++i) {                   // 8192 half2 / 512 thr
            const int fi = t + i * 512;
            const int kp = fi >> 7, e = fi & 127;
            const int c  = kp >> 3, r = kp & 7;
            const int d  = (c << 4) + ((r & 3) << 2) + ((r >> 2) << 1);
            w_h[kp * WSTR + (e & 7) * 16 + (e >> 3)] = pk_h2(w[d * DD + e], w[(d + 1) * DD + e]);
        }
    }
    const float qe = q[e_lane];

    const int PN   = B >> 1;                 // batch pairs
    const int Pstr = gridDim.x * NGRP;
    const int P0   = blockIdx.x * NGRP + g;

    auto load_tile = [&](int batch, float4* F) {
        const float4* src = reinterpret_cast<const float4*>(nbv + (size_t)batch * NNB * DD);
        #pragma unroll
        for (int i = 0; i < 8; ++i) F[i] = src[128 * i + gt];
    };
    auto store_tile = [&](const float4* F, int slot) {
        uint32_t* dst = nbH_g + slot * 32 * SH;
        #pragma unroll
        for (int i = 0; i < 8; ++i) {
            uint2 hh;
            hh.x = pk_h2(F[i].x, F[i].y);
            hh.y = pk_h2(F[i].z, F[i].w);
            *reinterpret_cast<uint2*>(dst + (4 * i + wrow) * SH + 2 * lane) = hh;
        }
    };

    // ---- prologue: pair P0 -> slots 0,1 ----
    float s0 = 0.f, s1 = 0.f;
    if (P0 < PN) {
        float4 F[8];
        load_tile(2 * P0, F);
        s0 = self_v[(size_t)(2 * P0) * DD + e_lane];
        store_tile(F, 0);
        load_tile(2 * P0 + 1, F);
        s1 = self_v[(size_t)(2 * P0 + 1) * DD + e_lane];
        store_tile(F, 1);
    }
    __syncthreads();                 // w_h + all groups' slots 0,1 visible

    int it = 0;
    for (int P = P0; P < PN; P += Pstr, ++it) {
        const int base  = (it & 1) * 2;          // slots read this iter
        const int nbase = 2 - base;              // slots written for next iter

        // ---- prefetch T0 (next pair, batch 0) + both next selfs ----
        const int Pn = P + Pstr;
        const bool have = (Pn < PN);
        float4 F[8];
        float sn0 = 0.f, sn1 = 0.f;
        if (have) {
            load_tile(2 * Pn, F);
            sn0 = self_v[(size_t)(2 * Pn) * DD + e_lane];
            sn1 = self_v[(size_t)(2 * Pn + 1) * DD + e_lane];
        }

        // ---- hi/lo for both batches (warp-private) ----
        {
            const float sq0 = s0 * qe, aq0 = LRELU_ALPHA * sq0;
            hl_w[lane] = (s0 >= 0.f) ? make_float2(sq0, aq0) : make_float2(aq0, sq0);
            const float sq1 = s1 * qe, aq1 = LRELU_ALPHA * sq1;
            hl_w[NNB + lane] = (s1 >= 0.f) ? make_float2(sq1, aq1) : make_float2(aq1, sq1);
        }
        __syncwarp();

        // ---- dual fp16 MMA mainloop: B fragments loaded ONCE for both tiles ----
        float acc[2][2][4][4];                   // [batch][T][j][frag]
        #pragma unroll
        for (int b = 0; b < 2; ++b)
            #pragma unroll
            for (int T = 0; T < 2; ++T)
                #pragma unroll
                for (int j = 0; j < 4; ++j)
                    #pragma unroll
                    for (int k = 0; k < 4; ++k) acc[b][T][j][k] = 0.f;

        const uint32_t* a0p = nbH_g + base * 32 * SH + qr * SH + 2 * qc;
        const uint32_t* a1p = a0p + 32 * SH;
        const uint32_t* wp  = w_h + qc * WSTR + qr * 16 + 4 * eb;

        #pragma unroll
        for (int k0 = 0; k0 < DD; k0 += 16) {
            const int kh = k0 >> 1;
            const uint2 A0 = *reinterpret_cast<const uint2*>(a0p + kh);
            const uint2 A1 = *reinterpret_cast<const uint2*>(a0p + 8 * SH + kh);
            const uint2 A2 = *reinterpret_cast<const uint2*>(a0p + 16 * SH + kh);
            const uint2 A3 = *reinterpret_cast<const uint2*>(a0p + 24 * SH + kh);
            const uint2 C0 = *reinterpret_cast<const uint2*>(a1p + kh);
            const uint2 C1 = *reinterpret_cast<const uint2*>(a1p + 8 * SH + kh);
            const uint2 C2 = *reinterpret_cast<const uint2*>(a1p + 16 * SH + kh);
            const uint2 C3 = *reinterpret_cast<const uint2*>(a1p + 24 * SH + kh);
            const uint4 B0 = *reinterpret_cast<const uint4*>(wp + kh * WSTR);
            const uint4 B1 = *reinterpret_cast<const uint4*>(wp + (kh + 4) * WSTR);

            mma_f16(acc[0][0][0][0],acc[0][0][0][1],acc[0][0][0][2],acc[0][0][0][3], A0.x,A1.x,A0.y,A1.y, B0.x,B1.x);
            mma_f16(acc[0][1][0][0],acc[0][1][0][1],acc[0][1][0][2],acc[0][1][0][3], A2.x,A3.x,A2.y,A3.y, B0.x,B1.x);
            mma_f16(acc[1][0][0][0],acc[1][0][0][1],acc[1][0][0][2],acc[1][0][0][3], C0.x,C1.x,C0.y,C1.y, B0.x,B1.x);
            mma_f16(acc[1][1][0][0],acc[1][1][0][1],acc[1][1][0][2],acc[1][1][0][3], C2.x,C3.x,C2.y,C3.y, B0.x,B1.x);
            mma_f16(acc[0][0][1][0],acc[0][0][1][1],acc[0][0][1][2],acc[0][0][1][3], A0.x,A1.x,A0.y,A1.y, B0.y,B1.y);
            mma_f16(acc[0][1][1][0],acc[0][1][1][1],acc[0][1][1][2],acc[0][1][1][3], A2.x,A3.x,A2.y,A3.y, B0.y,B1.y);
            mma_f16(acc[1][0][1][0],acc[1][0][1][1],acc[1][0][1][2],acc[1][0][1][3], C0.x,C1.x,C0.y,C1.y, B0.y,B1.y);
            mma_f16(acc[1][1][1][0],acc[1][1][1][1],acc[1][1][1][2],acc[1][1][1][3], C2.x,C3.x,C2.y,C3.y, B0.y,B1.y);
            mma_f16(acc[0][0][2][0],acc[0][0][2][1],acc[0][0][2][2],acc[0][0][2][3], A0.x,A1.x,A0.y,A1.y, B0.z,B1.z);
            mma_f16(acc[0][1][2][0],acc[0][1][2][1],acc[0][1][2][2],acc[0][1][2][3], A2.x,A3.x,A2.y,A3.y, B0.z,B1.z);
            mma_f16(acc[1][0][2][0],acc[1][0][2][1],acc[1][0][2][2],acc[1][0][2][3], C0.x,C1.x,C0.y,C1.y, B0.z,B1.z);
            mma_f16(acc[1][1][2][0],acc[1][1][2][1],acc[1][1][2][2],acc[1][1][2][3], C2.x,C3.x,C2.y,C3.y, B0.z,B1.z);
            mma_f16(acc[0][0][3][0],acc[0][0][3][1],acc[0][0][3][2],acc[0][0][3][3], A0.x,A1.x,A0.y,A1.y, B0.w,B1.w);
            mma_f16(acc[0][1][3][0],acc[0][1][3][1],acc[0][1][3][2],acc[0][1][3][3], A2.x,A3.x,A2.y,A3.y, B0.w,B1.w);
            mma_f16(acc[1][0][3][0],acc[1][0][3][1],acc[1][0][3][2],acc[1][0][3][3], C0.x,C1.x,C0.y,C1.y, B0.w,B1.w);
            mma_f16(acc[1][1][3][0],acc[1][1][3][1],acc[1][1][3][2],acc[1][1][3][3], C2.x,C3.x,C2.y,C3.y, B0.w,B1.w);
        }

        // ---- score partials via hi/lo, both batches ----
        #pragma unroll
        for (int b = 0; b < 2; ++b) {
            float pr[4] = {0.f, 0.f, 0.f, 0.f};
            #pragma unroll
            for (int j = 0; j < 4; ++j) {
                const float2 H0 = hl_w[b * NNB + 8 * j + 2 * qc];
                const float2 H1 = hl_w[b * NNB + 8 * j + 2 * qc + 1];
                #pragma unroll
                for (int T = 0; T < 2; ++T) {
                    float m;
                    m = acc[b][T][j][0]; pr[2*T]   = fmaf((m >= 0.f) ? H0.x : H0.y, m, pr[2*T]);
                    m = acc[b][T][j][1]; pr[2*T]   = fmaf((m >= 0.f) ? H1.x : H1.y, m, pr[2*T]);
                    m = acc[b][T][j][2]; pr[2*T+1] = fmaf((m >= 0.f) ? H0.x : H0.y, m, pr[2*T+1]);
                    m = acc[b][T][j][3]; pr[2*T+1] = fmaf((m >= 0.f) ? H1.x : H1.y, m, pr[2*T+1]);
                }
            }
            #pragma unroll
            for (int i = 0; i < 4; ++i) {
                pr[i] += __shfl_xor_sync(0xffffffffu, pr[i], 1);
                pr[i] += __shfl_xor_sync(0xffffffffu, pr[i], 2);
            }
            float* sg = scoreG + b * 128;
            if (qc == 0) {
                sg[eb * NNB + qr]      = pr[0];
                sg[eb * NNB + qr + 8]  = pr[1];
                sg[eb * NNB + qr + 16] = pr[2];
                sg[eb * NNB + qr + 24] = pr[3];
            }
        }
        barg(bid);                           // bar1: scores visible; slots[base] dead

        // ---- store T0 -> slot nbase; start T1 LDG (reusing F) ----
        if (have) {
            store_tile(F, nbase);
            load_tile(2 * Pn + 1, F);
        }

        // ---- softmax: warp0 -> batch0, warp1 -> batch1 (R12-identical order) ----
        if (eb < 2) {
            const float* sg = scoreG + eb * 128;
            const float s = sg[lane] + sg[NNB + lane]
                          + sg[2 * NNB + lane] + sg[3 * NNB + lane];
            float mx = s;
            #pragma unroll
            for (int o = 16; o > 0; o >>= 1)
                mx = fmaxf(mx, __shfl_xor_sync(0xffffffffu, mx, o));
            const float ex = __expf(s - mx);
            float sum = ex;
            #pragma unroll
            for (int o = 16; o > 0; o >>= 1)
                sum += __shfl_xor_sync(0xffffffffu, sum, o);
            alphaG[eb * NNB + lane] = ex / sum;
        }
        barg(bid);                           // bar2: alpha + T0 visible

        // ---- register epilogue, both batches, direct STG ----
        #pragma unroll
        for (int b = 0; b < 2; ++b) {
            const float* alb = alphaG + b * NNB;
            const float al0 = alb[qr];
            const float al1 = alb[qr + 8];
            const float al2 = alb[qr + 16];
            const float al3 = alb[qr + 24];
            float val[4][2];
            #pragma unroll
            for (int j = 0; j < 4; ++j)
                #pragma unroll
                for (int u = 0; u < 2; ++u) {
                    float v = al0 * acc[b][0][j][u];
                    v = fmaf(al1, acc[b][0][j][2 + u], v);
                    v = fmaf(al2, acc[b][1][j][u], v);
                    v = fmaf(al3, acc[b][1][j][2 + u], v);
                    v += __shfl_xor_sync(0xffffffffu, v, 4);
                    v += __shfl_xor_sync(0xffffffffu, v, 8);
                    v += __shfl_xor_sync(0xffffffffu, v, 16);
                    val[j][u] = v;
                }
            if (qr == 0) {
                float* op = out + (size_t)(2 * P + b) * DD + 32 * eb + 2 * qc;
                #pragma unroll
                for (int j = 0; j < 4; ++j) {
                    op[8 * j]     = val[j][0];
                    op[8 * j + 1] = val[j][1];
                }
            }
        }

        // ---- store T1 -> slot nbase+1, then make visible for next iter ----
        if (have) store_tile(F, nbase + 1);
        barg(bid);                           // bar3: T1 (+ leftovers) visible

        s0 = sn0;
        s1 = sn1;
    }
}

extern "C" void kernel_launch(void* const* d_in, const int* in_sizes, int n_in,
                              void* d_out, int out_size)
{
    const float* self_v = (const float*)d_in[0];   // [B,128]
    const float* nbv    = (const float*)d_in[1];   // [B,32,128]
    const float* w      = (const float*)d_in[2];   // [128,128]
    const float* q      = (const float*)d_in[3];   // [128,1]
    float*       out    = (float*)d_out;           // [B,128]

    const int B  = in_sizes[0] / DD;               // 20000
    const int PN = B / 2;                          // 10000 pairs

    int smc = 0;
    cudaDeviceGetAttribute(&smc, cudaDevAttrMultiProcessorCount, 0);
    if (smc <= 0) smc = 148;
    int grid = smc;
    if (grid * NGRP > PN) grid = (PN + NGRP - 1) / NGRP;

    const size_t smem_bytes =
        (size_t)(64 * WSTR + NGRP * 4 * 32 * SH      // w_h + nbH (u32)
                 + NGRP * 2 * 128                     // scoreP
                 + NGRP * 2 * NNB                     // alphaP
                 + NGRP * 4 * 2 * NNB * 2)            // hl_s
        * 4;                                          // 194,560 B

    cudaFuncSetAttribute(gat_h16f, cudaFuncAttributeMaxDynamicSharedMemorySize,
                         (int)smem_bytes);

    gat_h16f<<<grid, 512, smem_bytes>>>(self_v, nbv, w, q, out, B);
}

// round 16
// speedup vs baseline: 1.4113x; 1.4113x over previous
#include <cuda_runtime.h>
#include <cuda_fp16.h>
#include <cstdint>

#define DD    128
#define NNB   32
#define WSTR  132              // w_h stride (u32); fragment-major, re-paired k rows
#define SH    72               // nbH row stride (u32); conflict-free LDS.64/STS.64
#define NGRP  4
#define LRELU_ALPHA 0.2f

// w_h : "k-pair row" R = 8c + r (chunk c of 16 k's, r = 0..7):
//   r < 4 : half2 pair of physical k-rows (16c+4r, 16c+4r+1)
//   r >= 4: pair (16c+4(r-4)+2, +3)
//   within row: pos(e) = (e&7)*16 + (e>>3) (u32), conflict-free LDS.128.
// nbH : row n, entry j = half2(nb[n][2j], nb[n][2j+1]); ONE buffer per group
//   (registers hold the in-flight next tile). Self vector lives in a register.

__device__ __forceinline__ uint32_t pk_h2(float lo, float hi) {
    __half2 h = __floats2half2_rn(lo, hi);
    return *reinterpret_cast<uint32_t*>(&h);
}

__device__ __forceinline__ void mma_f16(float& c0, float& c1, float& c2, float& c3,
                                        uint32_t a0, uint32_t a1, uint32_t a2, uint32_t a3,
                                        uint32_t b0, uint32_t b1) {
    asm volatile(
        "mma.sync.aligned.m16n8k16.row.col.f32.f16.f16.f32 "
        "{%0,%1,%2,%3}, {%4,%5,%6,%7}, {%8,%9}, {%0,%1,%2,%3};"
        : "+f"(c0), "+f"(c1), "+f"(c2), "+f"(c3)
        : "r"(a0), "r"(a1), "r"(a2), "r"(a3), "r"(b0), "r"(b1));
}

__device__ __forceinline__ void barg(int id) {
    asm volatile("bar.sync %0, 128;" :: "r"(id) : "memory");
}

extern "C" __global__ void __launch_bounds__(512, 1)
gat_h16g(const float* __restrict__ self_v,
         const float* __restrict__ nbv,
         const float* __restrict__ w,
         const float* __restrict__ q,
         float* __restrict__ out,
         int B)
{
    extern __shared__ float sm[];
    uint32_t* w_h  = reinterpret_cast<uint32_t*>(sm);    // 64*132 = 8448 u32
    uint32_t* nbH  = w_h + 64 * WSTR;                    // 4 grp * 32*72 = 9216 u32
    float* scoreP  = sm + 8448 + 9216;                   // 4 grp * 128 = 512 f
    float* alpha_s = scoreP + NGRP * 128;                // 4 grp * 32 = 128 f
    float* hl_s    = alpha_s + NGRP * NNB;               // 4*4*32*2 = 1024 f

    const int t    = threadIdx.x;
    const int lane = t & 31;
    const int ww   = t >> 5;
    const int g    = ww >> 2;
    const int eb   = ww & 3;
    const int gt   = t & 127;
    const int wrow = gt >> 5;
    const int qr   = lane >> 2;
    const int qc   = lane & 3;
    const int bid  = g + 1;
    const int e_lane = 32 * eb + lane;     // this thread's own e index

    uint32_t* nbH_g  = nbH + g * 32 * SH;
    float*    scoreG = scoreP + g * 128;
    float*    alpha_g = alpha_s + g * NNB;
    float2*   hl_w   = reinterpret_cast<float2*>(hl_s) + (g * 4 + eb) * NNB;

    // ---- one-time: w -> fp16 re-paired k rows, fragment-major (RN) ----
    {
        #pragma unroll
        for (int i = 0; i < 16; ++i) {                   // 8192 half2 / 512 thr
            const int fi = t + i * 512;
            const int kp = fi >> 7, e = fi & 127;
            const int c  = kp >> 3, r = kp & 7;
            const int d  = (c << 4) + ((r & 3) << 2) + ((r >> 2) << 1);
            w_h[kp * WSTR + (e & 7) * 16 + (e >> 3)] = pk_h2(w[d * DD + e], w[(d + 1) * DD + e]);
        }
    }
    const float qe = q[e_lane];

    const int stride = gridDim.x * NGRP;
    const int p0     = blockIdx.x * NGRP + g;

    // pack 8 float4 (fp32 tile slice) into the group f16 buffer.
    // LDG i of thread gt covers fp32 offsets 512i+4gt -> row 4i+wrow, cols 4*lane..+3
    auto store_tile = [&](const float4* F) {
        #pragma unroll
        for (int i = 0; i < 8; ++i) {
            uint2 hh;
            hh.x = pk_h2(F[i].x, F[i].y);
            hh.y = pk_h2(F[i].z, F[i].w);
            *reinterpret_cast<uint2*>(nbH_g + (4 * i + wrow) * SH + 2 * lane) = hh;
        }
    };

    // ---- prologue: tile p0 -> buffer; self -> register ----
    float s_cur = 0.f;
    if (p0 < B) {
        float4 F[8];
        const float4* src = reinterpret_cast<const float4*>(nbv + (size_t)p0 * NNB * DD);
        #pragma unroll
        for (int i = 0; i < 8; ++i) F[i] = src[128 * i + gt];
        s_cur = self_v[(size_t)p0 * DD + e_lane];
        store_tile(F);
    }
    __syncthreads();                 // w_h + all groups' tile-0 visible

    for (int p = p0; p < B; p += stride) {
        // ---- step0: LDG prefetch next batch (regs = 2nd buffer) ----
        const int pn = p + stride;
        const bool have = (pn < B);
        float4 F[8];
        float s_next = 0.f;
        if (have) {
            const float4* src = reinterpret_cast<const float4*>(nbv + (size_t)pn * NNB * DD);
            #pragma unroll
            for (int i = 0; i < 8; ++i) F[i] = src[128 * i + gt];
            s_next = self_v[(size_t)pn * DD + e_lane];
        }

        // ---- step1: warp-private hi/lo for this warp's 32 cols ----
        // lrelu(s*m)*q == m * (m>=0 ? hi : lo), hi/lo = s>=0 ? {sq,a*sq} : {a*sq,sq}
        {
            const float sq = s_cur * qe;
            const float aq = LRELU_ALPHA * sq;
            hl_w[lane] = (s_cur >= 0.f) ? make_float2(sq, aq) : make_float2(aq, sq);
        }
        __syncwarp();

        // ---- step2: fp16 MMA mainloop, warp tile 32x32, zero packing ----
        float acc[2][4][4];
        #pragma unroll
        for (int T = 0; T < 2; ++T)
            #pragma unroll
            for (int j = 0; j < 4; ++j)
                #pragma unroll
                for (int k = 0; k < 4; ++k) acc[T][j][k] = 0.f;

        const uint32_t* arH = nbH_g + qr * SH + 2 * qc;
        const uint32_t* wp  = w_h + qc * WSTR + qr * 16 + 4 * eb;

        #pragma unroll
        for (int k0 = 0; k0 < DD; k0 += 16) {
            const int kh = k0 >> 1;
            const uint2 A0 = *reinterpret_cast<const uint2*>(arH + kh);            // row qr
            const uint2 A1 = *reinterpret_cast<const uint2*>(arH + 8 * SH + kh);   // qr+8
            const uint2 A2 = *reinterpret_cast<const uint2*>(arH + 16 * SH + kh);  // 16+qr
            const uint2 A3 = *reinterpret_cast<const uint2*>(arH + 24 * SH + kh);  // 24+qr
            const uint4 B0 = *reinterpret_cast<const uint4*>(wp + kh * WSTR);
            const uint4 B1 = *reinterpret_cast<const uint4*>(wp + (kh + 4) * WSTR);

            mma_f16(acc[0][0][0],acc[0][0][1],acc[0][0][2],acc[0][0][3], A0.x,A1.x,A0.y,A1.y, B0.x,B1.x);
            mma_f16(acc[1][0][0],acc[1][0][1],acc[1][0][2],acc[1][0][3], A2.x,A3.x,A2.y,A3.y, B0.x,B1.x);
            mma_f16(acc[0][1][0],acc[0][1][1],acc[0][1][2],acc[0][1][3], A0.x,A1.x,A0.y,A1.y, B0.y,B1.y);
            mma_f16(acc[1][1][0],acc[1][1][1],acc[1][1][2],acc[1][1][3], A2.x,A3.x,A2.y,A3.y, B0.y,B1.y);
            mma_f16(acc[0][2][0],acc[0][2][1],acc[0][2][2],acc[0][2][3], A0.x,A1.x,A0.y,A1.y, B0.z,B1.z);
            mma_f16(acc[1][2][0],acc[1][2][1],acc[1][2][2],acc[1][2][3], A2.x,A3.x,A2.y,A3.y, B0.z,B1.z);
            mma_f16(acc[0][3][0],acc[0][3][1],acc[0][3][2],acc[0][3][3], A0.x,A1.x,A0.y,A1.y, B0.w,B1.w);
            mma_f16(acc[1][3][0],acc[1][3][1],acc[1][3][2],acc[1][3][3], A2.x,A3.x,A2.y,A3.y, B0.w,B1.w);
        }

        // ---- step3: score partials via hi/lo ----
        {
            float pr[4] = {0.f, 0.f, 0.f, 0.f};
            #pragma unroll
            for (int j = 0; j < 4; ++j) {
                const float2 H0 = hl_w[8 * j + 2 * qc];
                const float2 H1 = hl_w[8 * j + 2 * qc + 1];
                #pragma unroll
                for (int T = 0; T < 2; ++T) {
                    float m;
                    m = acc[T][j][0]; pr[2*T]   = fmaf((m >= 0.f) ? H0.x : H0.y, m, pr[2*T]);
                    m = acc[T][j][1]; pr[2*T]   = fmaf((m >= 0.f) ? H1.x : H1.y, m, pr[2*T]);
                    m = acc[T][j][2]; pr[2*T+1] = fmaf((m >= 0.f) ? H0.x : H0.y, m, pr[2*T+1]);
                    m = acc[T][j][3]; pr[2*T+1] = fmaf((m >= 0.f) ? H1.x : H1.y, m, pr[2*T+1]);
                }
            }
            #pragma unroll
            for (int i = 0; i < 4; ++i) {
                pr[i] += __shfl_xor_sync(0xffffffffu, pr[i], 1);
                pr[i] += __shfl_xor_sync(0xffffffffu, pr[i], 2);
            }
            if (qc == 0) {
                scoreG[eb * NNB + qr]      = pr[0];
                scoreG[eb * NNB + qr + 8]  = pr[1];
                scoreG[eb * NNB + qr + 16] = pr[2];
                scoreG[eb * NNB + qr + 24] = pr[3];
            }
        }
        barg(bid);                     // bar1: scores visible; nbH_g dead

        // ---- step5: pack + store NEXT tile into the group buffer ----
        if (have) store_tile(F);

        // ---- step6: softmax over 32 neighbors (warp 0 of group) ----
        if (eb == 0) {
            const float s = scoreG[lane] + scoreG[NNB + lane]
                          + scoreG[2 * NNB + lane] + scoreG[3 * NNB + lane];
            float mx = s;
            #pragma unroll
            for (int o = 16; o > 0; o >>= 1)
                mx = fmaxf(mx, __shfl_xor_sync(0xffffffffu, mx, o));
            const float ex = __expf(s - mx);
            float sum = ex;
            #pragma unroll
            for (int o = 16; o > 0; o >>= 1)
                sum += __shfl_xor_sync(0xffffffffu, sum, o);
            alpha_s[g * NNB + lane] = ex / sum;
        }
        barg(bid);                     // bar2: alpha + next tile visible

        // ---- step8: register epilogue, alpha from smem, direct STG ----
        {
            const float al0 = alpha_g[qr];
            const float al1 = alpha_g[qr + 8];
            const float al2 = alpha_g[qr + 16];
            const float al3 = alpha_g[qr + 24];
            float val[4][2];
            #pragma unroll
            for (int j = 0; j < 4; ++j)
                #pragma unroll
                for (int u = 0; u < 2; ++u) {
                    float v = al0 * acc[0][j][u];
                    v = fmaf(al1, acc[0][j][2 + u], v);
                    v = fmaf(al2, acc[1][j][u], v);
                    v = fmaf(al3, acc[1][j][2 + u], v);
                    v += __shfl_xor_sync(0xffffffffu, v, 4);
                    v += __shfl_xor_sync(0xffffffffu, v, 8);
                    v += __shfl_xor_sync(0xffffffffu, v, 16);
                    val[j][u] = v;
                }
            if (qr == 0) {
                float* op = out + (size_t)p * DD + 32 * eb + 2 * qc;
                #pragma unroll
                for (int j = 0; j < 4; ++j) {
                    op[8 * j]     = val[j][0];
                    op[8 * j + 1] = val[j][1];
                }
            }
        }

        s_cur = s_next;
    }
}

extern "C" void kernel_launch(void* const* d_in, const int* in_sizes, int n_in,
                              void* d_out, int out_size)
{
    const float* self_v = (const float*)d_in[0];   // [B,128]
    const float* nbv    = (const float*)d_in[1];   // [B,32,128]
    const float* w      = (const float*)d_in[2];   // [128,128]
    const float* q      = (const float*)d_in[3];   // [128,1]
    float*       out    = (float*)d_out;           // [B,128]

    const int B = in_sizes[0] / DD;                // 20000

    int smc = 0;
    cudaDeviceGetAttribute(&smc, cudaDevAttrMultiProcessorCount, 0);
    if (smc <= 0) smc = 148;
    int grid = smc;
    if (grid * NGRP > B) grid = (B + NGRP - 1) / NGRP;

    const size_t smem_bytes =
        (size_t)(64 * WSTR + NGRP * 32 * SH          // w_h + nbH (u32)
                 + NGRP * 128                         // scoreP
                 + NGRP * NNB                         // alpha_s
                 + NGRP * 4 * NNB * 2)                // hl_s
        * 4;                                          // 77,312 B

    cudaFuncSetAttribute(gat_h16g, cudaFuncAttributeMaxDynamicSharedMemorySize,
                         (int)smem_bytes);

    gat_h16g<<<grid, 512, smem_bytes>>>(self_v, nbv, w, q, out, B);
}

// round 17
// speedup vs baseline: 1.5038x; 1.0655x over previous
#include <cuda_runtime.h>
#include <cuda_fp16.h>
#include <cstdint>

#define DD    128
#define NNB   32
#define WSTR  132              // w_h stride (u32); fragment-major, re-paired k rows
#define SH    72               // nbH row stride (u32); conflict-free LDS.64/STS.64
#define NGRP  4
#define LRELU_ALPHA 0.2f

// w_h : "k-pair row" R = 8c + r (chunk c of 16 k's, r = 0..7):
//   r < 4 : half2 pair of physical k-rows (16c+4r, 16c+4r+1)
//   r >= 4: pair (16c+4(r-4)+2, +3)
//   within row: pos(e) = (e&7)*16 + (e>>3) (u32), conflict-free LDS.128.
// nbH : row n, entry j = half2(nb[n][2j], nb[n][2j+1]); ONE buffer per group.
// score trick: lrelu(s*m)*q == a*m + b*|m|, a = 0.6*s*q, b = sign(s)*0.4*s*q.

__device__ __forceinline__ uint32_t pk_h2(float lo, float hi) {
    __half2 h = __floats2half2_rn(lo, hi);
    return *reinterpret_cast<uint32_t*>(&h);
}

__device__ __forceinline__ void mma_f16(float& c0, float& c1, float& c2, float& c3,
                                        uint32_t a0, uint32_t a1, uint32_t a2, uint32_t a3,
                                        uint32_t b0, uint32_t b1) {
    asm volatile(
        "mma.sync.aligned.m16n8k16.row.col.f32.f16.f16.f32 "
        "{%0,%1,%2,%3}, {%4,%5,%6,%7}, {%8,%9}, {%0,%1,%2,%3};"
        : "+f"(c0), "+f"(c1), "+f"(c2), "+f"(c3)
        : "r"(a0), "r"(a1), "r"(a2), "r"(a3), "r"(b0), "r"(b1));
}

__device__ __forceinline__ void barg(int id) {
    asm volatile("bar.sync %0, 128;" :: "r"(id) : "memory");
}

extern "C" __global__ void __launch_bounds__(512, 1)
gat_h16h(const float* __restrict__ self_v,
         const float* __restrict__ nbv,
         const float* __restrict__ w,
         const float* __restrict__ q,
         float* __restrict__ out,
         int B)
{
    extern __shared__ float sm[];
    uint32_t* w_h  = reinterpret_cast<uint32_t*>(sm);    // 64*132 = 8448 u32
    uint32_t* nbH  = w_h + 64 * WSTR;                    // 4 grp * 32*72 = 9216 u32
    float* scoreP  = sm + 8448 + 9216;                   // 4 grp * 128 = 512 f
    float* alpha_s = scoreP + NGRP * 128;                // 4 grp * 32 = 128 f
    float* hl_s    = alpha_s + NGRP * NNB;               // 4*4*32*2 = 1024 f

    const int t    = threadIdx.x;
    const int lane = t & 31;
    const int ww   = t >> 5;
    const int g    = ww >> 2;
    const int eb   = ww & 3;
    const int gt   = t & 127;
    const int wrow = gt >> 5;
    const int qr   = lane >> 2;
    const int qc   = lane & 3;
    const int bid  = g + 1;
    const int e_lane = 32 * eb + lane;     // this thread's own e index

    uint32_t* nbH_g  = nbH + g * 32 * SH;
    float*    scoreG = scoreP + g * 128;
    float*    alpha_g = alpha_s + g * NNB;
    float2*   hl_w   = reinterpret_cast<float2*>(hl_s) + (g * 4 + eb) * NNB;

    // ---- one-time: w -> fp16 re-paired k rows, fragment-major (RN) ----
    {
        #pragma unroll
        for (int i = 0; i < 16; ++i) {                   // 8192 half2 / 512 thr
            const int fi = t + i * 512;
            const int kp = fi >> 7, e = fi & 127;
            const int c  = kp >> 3, r = kp & 7;
            const int d  = (c << 4) + ((r & 3) << 2) + ((r >> 2) << 1);
            w_h[kp * WSTR + (e & 7) * 16 + (e >> 3)] = pk_h2(w[d * DD + e], w[(d + 1) * DD + e]);
        }
    }
    const float qe = q[e_lane];

    const int stride = gridDim.x * NGRP;
    const int p0     = blockIdx.x * NGRP + g;

    // pack 8 float4 (fp32 tile slice) into the group f16 buffer.
    auto store_tile = [&](const float4* F) {
        #pragma unroll
        for (int i = 0; i < 8; ++i) {
            uint2 hh;
            hh.x = pk_h2(F[i].x, F[i].y);
            hh.y = pk_h2(F[i].z, F[i].w);
            *reinterpret_cast<uint2*>(nbH_g + (4 * i + wrow) * SH + 2 * lane) = hh;
        }
    };

    // ---- prologue: tile p0 -> buffer; self -> register ----
    float s_cur = 0.f;
    if (p0 < B) {
        float4 F[8];
        const float4* src = reinterpret_cast<const float4*>(nbv + (size_t)p0 * NNB * DD);
        #pragma unroll
        for (int i = 0; i < 8; ++i) F[i] = src[128 * i + gt];
        s_cur = self_v[(size_t)p0 * DD + e_lane];
        store_tile(F);
    }
    __syncthreads();                 // w_h + all groups' tile-0 visible

    for (int p = p0; p < B; p += stride) {
        // ---- step0: LDG prefetch next batch (regs = 2nd buffer) ----
        const int pn = p + stride;
        const bool have = (pn < B);
        float4 F[8];
        float s_next = 0.f;
        if (have) {
            const float4* src = reinterpret_cast<const float4*>(nbv + (size_t)pn * NNB * DD);
            #pragma unroll
            for (int i = 0; i < 8; ++i) F[i] = src[128 * i + gt];
            s_next = self_v[(size_t)pn * DD + e_lane];
        }

        // ---- step1: warp-private (a,b) coefficients: a*m + b*|m| ----
        {
            const float sq = s_cur * qe;
            const float a  = 0.5f * (1.f + LRELU_ALPHA) * sq;
            const float bb = 0.5f * (1.f - LRELU_ALPHA) * sq;
            hl_w[lane] = make_float2(a, (s_cur >= 0.f) ? bb : -bb);
        }
        __syncwarp();

        // ---- step2: fp16 MMA mainloop, warp tile 32x32, zero packing ----
        float acc[2][4][4];
        #pragma unroll
        for (int T = 0; T < 2; ++T)
            #pragma unroll
            for (int j = 0; j < 4; ++j)
                #pragma unroll
                for (int k = 0; k < 4; ++k) acc[T][j][k] = 0.f;

        const uint32_t* arH = nbH_g + qr * SH + 2 * qc;
        const uint32_t* wp  = w_h + qc * WSTR + qr * 16 + 4 * eb;

        #pragma unroll
        for (int k0 = 0; k0 < DD; k0 += 16) {
            const int kh = k0 >> 1;
            const uint2 A0 = *reinterpret_cast<const uint2*>(arH + kh);            // row qr
            const uint2 A1 = *reinterpret_cast<const uint2*>(arH + 8 * SH + kh);   // qr+8
            const uint2 A2 = *reinterpret_cast<const uint2*>(arH + 16 * SH + kh);  // 16+qr
            const uint2 A3 = *reinterpret_cast<const uint2*>(arH + 24 * SH + kh);  // 24+qr
            const uint4 B0 = *reinterpret_cast<const uint4*>(wp + kh * WSTR);
            const uint4 B1 = *reinterpret_cast<const uint4*>(wp + (kh + 4) * WSTR);

            mma_f16(acc[0][0][0],acc[0][0][1],acc[0][0][2],acc[0][0][3], A0.x,A1.x,A0.y,A1.y, B0.x,B1.x);
            mma_f16(acc[1][0][0],acc[1][0][1],acc[1][0][2],acc[1][0][3], A2.x,A3.x,A2.y,A3.y, B0.x,B1.x);
            mma_f16(acc[0][1][0],acc[0][1][1],acc[0][1][2],acc[0][1][3], A0.x,A1.x,A0.y,A1.y, B0.y,B1.y);
            mma_f16(acc[1][1][0],acc[1][1][1],acc[1][1][2],acc[1][1][3], A2.x,A3.x,A2.y,A3.y, B0.y,B1.y);
            mma_f16(acc[0][2][0],acc[0][2][1],acc[0][2][2],acc[0][2][3], A0.x,A1.x,A0.y,A1.y, B0.z,B1.z);
            mma_f16(acc[1][2][0],acc[1][2][1],acc[1][2][2],acc[1][2][3], A2.x,A3.x,A2.y,A3.y, B0.z,B1.z);
            mma_f16(acc[0][3][0],acc[0][3][1],acc[0][3][2],acc[0][3][3], A0.x,A1.x,A0.y,A1.y, B0.w,B1.w);
            mma_f16(acc[1][3][0],acc[1][3][1],acc[1][3][2],acc[1][3][3], A2.x,A3.x,A2.y,A3.y, B0.w,B1.w);
        }

        // ---- step3: score partials via a*m + b*|m| (pure FFMA) ----
        {
            float pr[4] = {0.f, 0.f, 0.f, 0.f};
            #pragma unroll
            for (int j = 0; j < 4; ++j) {
                const float2 H0 = hl_w[8 * j + 2 * qc];
                const float2 H1 = hl_w[8 * j + 2 * qc + 1];
                #pragma unroll
                for (int T = 0; T < 2; ++T) {
                    float m;
                    m = acc[T][j][0];
                    pr[2*T]   = fmaf(H0.x, m, pr[2*T]);   pr[2*T]   = fmaf(H0.y, fabsf(m), pr[2*T]);
                    m = acc[T][j][1];
                    pr[2*T]   = fmaf(H1.x, m, pr[2*T]);   pr[2*T]   = fmaf(H1.y, fabsf(m), pr[2*T]);
                    m = acc[T][j][2];
                    pr[2*T+1] = fmaf(H0.x, m, pr[2*T+1]); pr[2*T+1] = fmaf(H0.y, fabsf(m), pr[2*T+1]);
                    m = acc[T][j][3];
                    pr[2*T+1] = fmaf(H1.x, m, pr[2*T+1]); pr[2*T+1] = fmaf(H1.y, fabsf(m), pr[2*T+1]);
                }
            }
            #pragma unroll
            for (int i = 0; i < 4; ++i) {
                pr[i] += __shfl_xor_sync(0xffffffffu, pr[i], 1);
                pr[i] += __shfl_xor_sync(0xffffffffu, pr[i], 2);
            }
            if (qc == 0) {
                scoreG[eb * NNB + qr]      = pr[0];
                scoreG[eb * NNB + qr + 8]  = pr[1];
                scoreG[eb * NNB + qr + 16] = pr[2];
                scoreG[eb * NNB + qr + 24] = pr[3];
            }
        }
        barg(bid);                     // bar1: scores visible; nbH_g dead

        // ---- step5: pack + store NEXT tile into the group buffer ----
        if (have) store_tile(F);

        // ---- step6: softmax over 32 neighbors (warp 0 of group) ----
        if (eb == 0) {
            const float s = scoreG[lane] + scoreG[NNB + lane]
                          + scoreG[2 * NNB + lane] + scoreG[3 * NNB + lane];
            float mx = s;
            #pragma unroll
            for (int o = 16; o > 0; o >>= 1)
                mx = fmaxf(mx, __shfl_xor_sync(0xffffffffu, mx, o));
            const float ex = __expf(s - mx);
            float sum = ex;
            #pragma unroll
            for (int o = 16; o > 0; o >>= 1)
                sum += __shfl_xor_sync(0xffffffffu, sum, o);
            alpha_s[g * NNB + lane] = ex / sum;
        }
        barg(bid);                     // bar2: alpha + next tile visible

        // ---- step8: epilogue: alpha-weight, 7-shfl recursive halving, STG.32 ----
        {
            const float al0 = alpha_g[qr];
            const float al1 = alpha_g[qr + 8];
            const float al2 = alpha_g[qr + 16];
            const float al3 = alpha_g[qr + 24];
            float v[8];                        // idx = 2*j + u
            #pragma unroll
            for (int j = 0; j < 4; ++j)
                #pragma unroll
                for (int u = 0; u < 2; ++u) {
                    float x = al0 * acc[0][j][u];
                    x = fmaf(al1, acc[0][j][2 + u], x);
                    x = fmaf(al2, acc[1][j][u], x);
                    x = fmaf(al3, acc[1][j][2 + u], x);
                    v[2 * j + u] = x;
                }
            // reduce over qr (lanes xor 16, 8, 4), halving the value set
            #define RED_ROUND(o, cc) {                                    \
                const bool hb = (lane & (o)) != 0;                        \
                _Pragma("unroll")                                         \
                for (int i = 0; i < (cc); ++i) {                          \
                    const float a = hb ? v[(cc) + i] : v[i];              \
                    const float b = hb ? v[i] : v[(cc) + i];              \
                    v[i] = a + __shfl_xor_sync(0xffffffffu, b, (o));      \
                } }
            RED_ROUND(16, 4) RED_ROUND(8, 2) RED_ROUND(4, 1)
            #undef RED_ROUND
            // lane (qr,qc) holds idx = qr -> e = 32eb + 8*(qr>>1) + 2*qc + (qr&1)
            out[(size_t)p * DD + 32 * eb + 8 * (qr >> 1) + 2 * qc + (qr & 1)] = v[0];
        }

        s_cur = s_next;
    }
}

extern "C" void kernel_launch(void* const* d_in, const int* in_sizes, int n_in,
                              void* d_out, int out_size)
{
    const float* self_v = (const float*)d_in[0];   // [B,128]
    const float* nbv    = (const float*)d_in[1];   // [B,32,128]
    const float* w      = (const float*)d_in[2];   // [128,128]
    const float* q      = (const float*)d_in[3];   // [128,1]
    float*       out    = (float*)d_out;           // [B,128]

    const int B = in_sizes[0] / DD;                // 20000

    int smc = 0;
    cudaDeviceGetAttribute(&smc, cudaDevAttrMultiProcessorCount, 0);
    if (smc <= 0) smc = 148;
    int grid = smc;
    if (grid * NGRP > B) grid = (B + NGRP - 1) / NGRP;

    const size_t smem_bytes =
        (size_t)(64 * WSTR + NGRP * 32 * SH          // w_h + nbH (u32)
                 + NGRP * 128                         // scoreP
                 + NGRP * NNB                         // alpha_s
                 + NGRP * 4 * NNB * 2)                // hl_s
        * 4;                                          // 77,312 B

    cudaFuncSetAttribute(gat_h16h, cudaFuncAttributeMaxDynamicSharedMemorySize,
                         (int)smem_bytes);

    gat_h16h<<<grid, 512, smem_bytes>>>(self_v, nbv, w, q, out, B);
}